// round 3
// baseline (speedup 1.0000x reference)
#include <cuda_runtime.h>

#define BB  8
#define CC  256
#define NHD 8
#define HDD 32
#define SS  16384

// Scratch (allocation-free rule: __device__ globals)
__device__ float g_qp[BB * CC * SS];            // qp, then in-place softmaxed -> qs
__device__ float g_ctx[BB * NHD * HDD * HDD];   // sum_s exp(kp)*vp
__device__ float g_rsum[BB * NHD * HDD];        // sum_s exp(kp)
__device__ float g_M[BB * CC * CC];             // fused Wo*ctx/rowsum*scale

// ---------------------------------------------------------------- zero accums
__global__ void k_zero() {
    int i = blockIdx.x * 256 + threadIdx.x;
    if (i < BB * NHD * HDD * HDD) g_ctx[i] = 0.f;
    if (i < BB * NHD * HDD)       g_rsum[i] = 0.f;
}

// ------------------------------------------------- K1: projections + ctx epi
// CTA: (s-tile 128) x (head) x (batch). Computes 96x128 tile =
// [qp(32) ; kp(32) ; vp(32)] for one head. Writes qp; accumulates ctx/rowsum.
__global__ __launch_bounds__(256) void k_proj(
    const float* __restrict__ q,
    const float* __restrict__ wq, const float* __restrict__ bq,
    const float* __restrict__ wk, const float* __restrict__ bk,
    const float* __restrict__ wv, const float* __restrict__ bv)
{
    __shared__ __align__(16) float sbuf[8512];
    float* As = sbuf;          // [32][97]  (padded: avoid 32-way store conflicts)
    float* Bs = sbuf + 3104;   // [32][128]

    const int tid = threadIdx.x;
    const int tx = tid & 15, ty = tid >> 4;
    const int b = blockIdx.z, n = blockIdx.y;
    const int s0 = blockIdx.x * 128;

    float acc[6][8];
    #pragma unroll
    for (int r = 0; r < 6; r++) {
        int row = ty + 16 * r;
        int sec = row >> 5, hr = row & 31;
        const float* bias = (sec == 0) ? bq : (sec == 1) ? bk : bv;
        float b0 = bias[n * 32 + hr];
        #pragma unroll
        for (int c = 0; c < 8; c++) acc[r][c] = b0;
    }

    for (int k0 = 0; k0 < 256; k0 += 32) {
        // A: 96 rows (wq|wk|wv for head n) x 32 k, stored transposed
        for (int i = tid; i < 96 * 32; i += 256) {
            int row = i >> 5, kk = i & 31;
            int sec = row >> 5, hr = row & 31;
            const float* W = (sec == 0) ? wq : (sec == 1) ? wk : wv;
            As[kk * 97 + row] = W[(n * 32 + hr) * 256 + k0 + kk];
        }
        // B: q[b, k0..k0+31, s0..s0+127], float4 coalesced
        for (int i = tid; i < 32 * 32; i += 256) {
            int kk = i >> 5, c4 = i & 31;
            float4 v = *(const float4*)(q + (size_t)(b * 256 + k0 + kk) * SS + s0 + c4 * 4);
            *(float4*)(Bs + kk * 128 + c4 * 4) = v;
        }
        __syncthreads();
        #pragma unroll
        for (int kk = 0; kk < 32; kk++) {
            float a[6], bb[8];
            #pragma unroll
            for (int r = 0; r < 6; r++) a[r] = As[kk * 97 + ty + 16 * r];
            #pragma unroll
            for (int c = 0; c < 8; c++) bb[c] = Bs[kk * 128 + tx + 16 * c];
            #pragma unroll
            for (int r = 0; r < 6; r++)
                #pragma unroll
                for (int c = 0; c < 8; c++)
                    acc[r][c] += a[r] * bb[c];
        }
        __syncthreads();
    }

    // Epilogue: qp -> global; exp(kp), vp -> SMEM (reuse sbuf, pad 133)
    float* Ek = sbuf;          // [32][133]
    float* Vt = sbuf + 4256;   // [32][133]

    #pragma unroll
    for (int r = 0; r < 6; r++) {
        int row = ty + 16 * r;
        #pragma unroll
        for (int c = 0; c < 8; c++) {
            int col = tx + 16 * c;
            float v = acc[r][c];
            if (r < 2)      g_qp[(size_t)(b * 256 + n * 32 + row) * SS + s0 + col] = v;
            else if (r < 4) Ek[(row - 32) * 133 + col] = expf(v);
            else            Vt[(row - 64) * 133 + col] = v;
        }
    }
    __syncthreads();

    // rowsum(exp(kp)) partials: warp w handles rows 4w..4w+3
    {
        int w = tid >> 5, lane = tid & 31;
        #pragma unroll
        for (int rr = 0; rr < 4; rr++) {
            int i = w * 4 + rr;
            float s = 0.f;
            #pragma unroll
            for (int c = lane; c < 128; c += 32) s += Ek[i * 133 + c];
            #pragma unroll
            for (int off = 16; off > 0; off >>= 1)
                s += __shfl_xor_sync(0xffffffffu, s, off);
            if (lane == 0) atomicAdd(&g_rsum[(b * 8 + n) * 32 + i], s);
        }
    }
    // ctx partials: thread -> (i, j0..j0+3), dot over 128 spatials
    {
        int i = tid >> 3;
        int j0 = (tid & 7) * 4;
        float c0 = 0.f, c1 = 0.f, c2 = 0.f, c3 = 0.f;
        #pragma unroll 4
        for (int s = 0; s < 128; s++) {
            float e = Ek[i * 133 + s];
            c0 += e * Vt[(j0 + 0) * 133 + s];
            c1 += e * Vt[(j0 + 1) * 133 + s];
            c2 += e * Vt[(j0 + 2) * 133 + s];
            c3 += e * Vt[(j0 + 3) * 133 + s];
        }
        float* dst = &g_ctx[(((b * 8 + n) * 32) + i) * 32 + j0];
        atomicAdd(dst + 0, c0);
        atomicAdd(dst + 1, c1);
        atomicAdd(dst + 2, c2);
        atomicAdd(dst + 3, c3);
    }
}

// --------------------------------------- K2a: per-pixel softmax over d (in place)
__global__ __launch_bounds__(128) void k_qsoft() {
    int b = blockIdx.z, n = blockIdx.y;
    int s = blockIdx.x * 128 + threadIdx.x;
    size_t base = (size_t)(b * 256 + n * 32) * SS + s;
    float v[32];
    float sum = 0.f;
    #pragma unroll
    for (int i = 0; i < 32; i++) { v[i] = expf(g_qp[base + (size_t)i * SS]); sum += v[i]; }
    float inv = 1.f / sum;
    #pragma unroll
    for (int i = 0; i < 32; i++) g_qp[base + (size_t)i * SS] = v[i] * inv;
}

// ------------------- K2b: M_b[o, n*32+i] = scale * sum_j Wo[o,n*32+j]*ctx / rsum
__global__ __launch_bounds__(256) void k_M(const float* __restrict__ wo) {
    int o = blockIdx.x, b = blockIdx.y;
    int t = threadIdx.x;
    int n = t >> 5, i = t & 31;
    const float* ct = &g_ctx[((b * 8 + n) * 32 + i) * 32];
    const float* wr = &wo[o * 256 + n * 32];
    float s = 0.f;
    #pragma unroll
    for (int j = 0; j < 32; j++) s += wr[j] * ct[j];
    g_M[(b * 256 + o) * 256 + t] =
        s * 0.17677669529663687f / g_rsum[(b * 8 + n) * 32 + i];  // d^-0.5 = 32^-0.5
}

// ---------------------------- K3: final GEMM  out[b,o,s] = bo[o] + M_b @ qs
__global__ __launch_bounds__(256) void k_out(const float* __restrict__ bo,
                                             float* __restrict__ out)
{
    __shared__ __align__(16) float As[32 * 129];
    __shared__ __align__(16) float Bs[32 * 128];
    const int tid = threadIdx.x;
    const int tx = tid & 15, ty = tid >> 4;
    const int b = blockIdx.z;
    const int o0 = blockIdx.y * 128;
    const int s0 = blockIdx.x * 128;

    float acc[8][8];
    #pragma unroll
    for (int r = 0; r < 8; r++) {
        float b0 = bo[o0 + ty + 16 * r];
        #pragma unroll
        for (int c = 0; c < 8; c++) acc[r][c] = b0;
    }

    for (int k0 = 0; k0 < 256; k0 += 32) {
        for (int i = tid; i < 128 * 32; i += 256) {
            int row = i >> 5, kk = i & 31;
            As[kk * 129 + row] = g_M[(size_t)(b * 256 + o0 + row) * 256 + k0 + kk];
        }
        for (int i = tid; i < 32 * 32; i += 256) {
            int kk = i >> 5, c4 = i & 31;
            float4 v = *(const float4*)(g_qp + (size_t)(b * 256 + k0 + kk) * SS + s0 + c4 * 4);
            *(float4*)(Bs + kk * 128 + c4 * 4) = v;
        }
        __syncthreads();
        #pragma unroll
        for (int kk = 0; kk < 32; kk++) {
            float a[8], bb[8];
            #pragma unroll
            for (int r = 0; r < 8; r++) a[r] = As[kk * 129 + ty + 16 * r];
            #pragma unroll
            for (int c = 0; c < 8; c++) bb[c] = Bs[kk * 128 + tx + 16 * c];
            #pragma unroll
            for (int r = 0; r < 8; r++)
                #pragma unroll
                for (int c = 0; c < 8; c++)
                    acc[r][c] += a[r] * bb[c];
        }
        __syncthreads();
    }

    #pragma unroll
    for (int r = 0; r < 8; r++) {
        int o = o0 + ty + 16 * r;
        #pragma unroll
        for (int c = 0; c < 8; c++)
            out[(size_t)(b * 256 + o) * SS + s0 + tx + 16 * c] = acc[r][c];
    }
}

// ---------------------------------------------------------------------------
extern "C" void kernel_launch(void* const* d_in, const int* in_sizes, int n_in,
                              void* d_out, int out_size)
{
    const float* q  = (const float*)d_in[0];
    const float* wq = (const float*)d_in[1];
    const float* bq = (const float*)d_in[2];
    const float* wk = (const float*)d_in[3];
    const float* bk = (const float*)d_in[4];
    const float* wv = (const float*)d_in[5];
    const float* bv = (const float*)d_in[6];
    const float* wo = (const float*)d_in[7];
    const float* bo = (const float*)d_in[8];
    float* out = (float*)d_out;

    k_zero<<<256, 256>>>();
    k_proj<<<dim3(SS / 128, NHD, BB), 256>>>(q, wq, bq, wk, bk, wv, bv);
    k_qsoft<<<dim3(SS / 128, NHD, BB), 128>>>();
    k_M<<<dim3(CC, BB), 256>>>(wo);
    k_out<<<dim3(SS / 128, CC / 128, BB), 256>>>(bo, out);
}